// round 7
// baseline (speedup 1.0000x reference)
#include <cuda_runtime.h>
#include <math.h>

#define BB 2
#define N1 384
#define N2 384
#define DD 128
#define HH 128
#define LL 3
#define NF 54

// ---------------- scratch (device globals; no allocation) ----------------
static __device__ float g_h1g[BB*N1*DD];
static __device__ float g_h2g[BB*N2*DD];
static __device__ float g_hX [2*BB*N1*DD];   // ping-pong h
static __device__ float g_hAX[2*BB*N1*DD];   // ping-pong hA
static __device__ float g_E  [BB*N1*N1];     // symmetric e = P + P^T
static __device__ float g_m  [BB*N1];
static __device__ float g_iz [BB*N1];
static __device__ float g_p1 [5*BB*N1*HH];
static __device__ float g_p2 [5*BB*N2*HH];
static __device__ float g_WA [LL*DD*DD];
static __device__ float g_bA [LL*DD];
static __device__ float g_pec[576];
static __device__ float g_pev[576];

__device__ __forceinline__ float sigmoidf_(float x){ return 1.f/(1.f+__expf(-x)); }

// ---------------- fused: WA=W@A, bA=Wb@A  +  node projection ----------------
__global__ __launch_bounds__(128) void k_pre_node(const float* __restrict__ W,
                                                  const float* __restrict__ Wb,
                                                  const float* __restrict__ A,
                                                  const float* __restrict__ h1,
                                                  const float* __restrict__ h2,
                                                  const float* __restrict__ nW){
    int bi = blockIdx.x, d = threadIdx.x;
    if (bi < LL*DD){
        int l = bi / DD, k = bi % DD;
        __shared__ float sw[DD];
        __shared__ float sb[DD];
        sw[d] = W[(l*DD + k)*DD + d];
        if (k == 0) sb[d] = Wb[l*DD + d];
        __syncthreads();
        const float* Al = A + l*DD*DD;
        float acc = 0.f;
        #pragma unroll 4
        for (int m = 0; m < DD; m++) acc += sw[m]*Al[m*DD + d];
        g_WA[(l*DD + k)*DD + d] = acc;
        if (k == 0){
            float bacc = 0.f;
            #pragma unroll 4
            for (int m = 0; m < DD; m++) bacc += sb[m]*Al[m*DD + d];
            g_bA[l*DD + d] = bacc;
        }
    } else {
        int r0 = (bi - LL*DD)*4;
        __shared__ float sx[4][NF];
        bool lig = (r0 < BB*N1);
        const float* src = lig ? (h1 + r0*NF) : (h2 + (r0 - BB*N1)*NF);
        for (int idx = d; idx < 4*NF; idx += 128) ((float*)sx)[idx] = src[idx];
        __syncthreads();
        float acc[4] = {0.f,0.f,0.f,0.f};
        #pragma unroll 2
        for (int k = 0; k < NF; k++){
            float wv = nW[k*DD + d];
            #pragma unroll
            for (int ii = 0; ii < 4; ii++) acc[ii] += sx[ii][k]*wv;
        }
        float* dst = lig ? (g_h1g + r0*DD) : (g_h2g + (r0 - BB*N1)*DD);
        #pragma unroll
        for (int ii = 0; ii < 4; ii++) dst[ii*DD + d] = acc[ii];
    }
}

// ---------------- stage2: gat_h layer0 (96 blocks) + protein pair-proj (240 blocks) ----------------
__global__ __launch_bounds__(128) void k_stage2(const float* __restrict__ gatW,
                                                const float* __restrict__ gatWb,
                                                const float* __restrict__ W1){
    int bi = blockIdx.x, d = threadIdx.x;
    __shared__ float sx[16][DD];
    if (bi < 96){
        int r0 = bi*8;
        #pragma unroll
        for (int ii = 0; ii < 8; ii++) sx[ii][d] = g_h1g[(r0 + ii)*DD + d];
        __syncthreads();
        float wb = gatWb[d], bav = g_bA[d];
        float h[8], ha[8];
        #pragma unroll
        for (int ii = 0; ii < 8; ii++){ h[ii] = wb; ha[ii] = bav; }
        #pragma unroll 2
        for (int k = 0; k < DD; k++){
            float wv  = gatW[k*DD + d];
            float wav = g_WA[k*DD + d];
            #pragma unroll
            for (int ii = 0; ii < 8; ii++){
                h [ii] += sx[ii][k]*wv;
                ha[ii] += sx[ii][k]*wav;
            }
        }
        #pragma unroll
        for (int ii = 0; ii < 8; ii++){
            g_hX [(r0 + ii)*DD + d] = h [ii];
            g_hAX[(r0 + ii)*DD + d] = ha[ii];
        }
    } else {
        int pi = bi - 96;
        int m  = pi / 48;
        int r0 = (pi % 48)*16;
        #pragma unroll
        for (int ii = 0; ii < 16; ii++) sx[ii][d] = g_h2g[(r0 + ii)*DD + d];
        __syncthreads();
        const float* W = W1 + m*2*DD*HH + DD*HH;   // protein half, no bias
        float acc[16];
        #pragma unroll
        for (int ii = 0; ii < 16; ii++) acc[ii] = 0.f;
        #pragma unroll 2
        for (int k = 0; k < DD; k++){
            float wv = W[k*HH + d];
            #pragma unroll
            for (int ii = 0; ii < 16; ii++) acc[ii] = fmaf(sx[ii][k], wv, acc[ii]);
        }
        #pragma unroll
        for (int ii = 0; ii < 16; ii++) g_p2[(m*BB*N2 + r0 + ii)*HH + d] = acc[ii];
    }
}

// ---------------- E = hA@h^T + h@hA^T (symmetric), 32j x 64k tiles ----------------
// dynamic smem: sAj[64][36] + sBj[64][36] + sAk[64][68] + sBk[64][68]
#define E_SMEM ((64*36*2 + 64*68*2)*4)
__global__ __launch_bounds__(256) void k_e(int cur){
    extern __shared__ float sm[];
    float* sAj = sm;                 // hA rows j-tile, [kk][row<32]
    float* sBj = sm + 64*36;         // h  rows j-tile
    float* sAk = sm + 64*36*2;       // hA rows k-tile, [kk][row<64]
    float* sBk = sm + 64*36*2 + 64*68;  // h rows k-tile
    const float* hb  = g_hX  + cur*BB*N1*DD;
    const float* hab = g_hAX + cur*BB*N1*DD;
    int b = blockIdx.z, j0 = blockIdx.y*32, k0 = blockIdx.x*64;
    int tid = threadIdx.x;
    int tx = tid & 15, ty = tid >> 4;
    float acc[2][4], accT[2][4];
    #pragma unroll
    for (int r = 0; r < 2; r++)
        #pragma unroll
        for (int c = 0; c < 4; c++){ acc[r][c] = 0.f; accT[r][c] = 0.f; }
    const float* baseAj = hab + (b*N1 + j0)*DD;
    const float* baseBj = hb  + (b*N1 + j0)*DD;
    const float* baseAk = hab + (b*N1 + k0)*DD;
    const float* baseBk = hb  + (b*N1 + k0)*DD;
    for (int ks = 0; ks < 2; ks++){
        __syncthreads();
        #pragma unroll
        for (int q = 0; q < 2; q++){
            int idx = tid + q*256;
            int row = idx & 31, kq = idx >> 5;
            float4 va = *(const float4*)(baseAj + row*DD + ks*64 + kq*4);
            sAj[(kq*4+0)*36 + row] = va.x; sAj[(kq*4+1)*36 + row] = va.y;
            sAj[(kq*4+2)*36 + row] = va.z; sAj[(kq*4+3)*36 + row] = va.w;
            float4 vb = *(const float4*)(baseBj + row*DD + ks*64 + kq*4);
            sBj[(kq*4+0)*36 + row] = vb.x; sBj[(kq*4+1)*36 + row] = vb.y;
            sBj[(kq*4+2)*36 + row] = vb.z; sBj[(kq*4+3)*36 + row] = vb.w;
        }
        #pragma unroll
        for (int q = 0; q < 4; q++){
            int idx = tid + q*256;
            int row = idx & 63, kq = idx >> 6;
            float4 va = *(const float4*)(baseAk + row*DD + ks*64 + kq*4);
            sAk[(kq*4+0)*68 + row] = va.x; sAk[(kq*4+1)*68 + row] = va.y;
            sAk[(kq*4+2)*68 + row] = va.z; sAk[(kq*4+3)*68 + row] = va.w;
            float4 vb = *(const float4*)(baseBk + row*DD + ks*64 + kq*4);
            sBk[(kq*4+0)*68 + row] = vb.x; sBk[(kq*4+1)*68 + row] = vb.y;
            sBk[(kq*4+2)*68 + row] = vb.z; sBk[(kq*4+3)*68 + row] = vb.w;
        }
        __syncthreads();
        #pragma unroll 4
        for (int kk = 0; kk < 64; kk++){
            float2 aj = *(const float2*)&sAj[kk*36 + ty*2];
            float2 bj = *(const float2*)&sBj[kk*36 + ty*2];
            float4 ak = *(const float4*)&sAk[kk*68 + tx*4];
            float4 bk = *(const float4*)&sBk[kk*68 + tx*4];
            acc [0][0] = fmaf(aj.x, bk.x, acc [0][0]);
            acc [0][1] = fmaf(aj.x, bk.y, acc [0][1]);
            acc [0][2] = fmaf(aj.x, bk.z, acc [0][2]);
            acc [0][3] = fmaf(aj.x, bk.w, acc [0][3]);
            acc [1][0] = fmaf(aj.y, bk.x, acc [1][0]);
            acc [1][1] = fmaf(aj.y, bk.y, acc [1][1]);
            acc [1][2] = fmaf(aj.y, bk.z, acc [1][2]);
            acc [1][3] = fmaf(aj.y, bk.w, acc [1][3]);
            accT[0][0] = fmaf(bj.x, ak.x, accT[0][0]);
            accT[0][1] = fmaf(bj.x, ak.y, accT[0][1]);
            accT[0][2] = fmaf(bj.x, ak.z, accT[0][2]);
            accT[0][3] = fmaf(bj.x, ak.w, accT[0][3]);
            accT[1][0] = fmaf(bj.y, ak.x, accT[1][0]);
            accT[1][1] = fmaf(bj.y, ak.y, accT[1][1]);
            accT[1][2] = fmaf(bj.y, ak.z, accT[1][2]);
            accT[1][3] = fmaf(bj.y, ak.w, accT[1][3]);
        }
    }
    #pragma unroll
    for (int r = 0; r < 2; r++){
        float4 o = make_float4(acc[r][0] + accT[r][0], acc[r][1] + accT[r][1],
                               acc[r][2] + accT[r][2], acc[r][3] + accT[r][3]);
        *(float4*)&g_E[(size_t)(b*N1 + j0 + ty*2 + r)*N1 + k0 + tx*4] = o;
    }
}

// ---------------- per-row stats (== per-column by symmetry): m, invZ ----------------
__global__ __launch_bounds__(256) void k_stats(const float* __restrict__ adj){
    int w = threadIdx.x >> 5, lane = threadIdx.x & 31;
    int rg = blockIdx.x*8 + w;                 // global row 0..767
    const float* er = g_E + (size_t)rg*N1;
    const float* ar = adj + (size_t)rg*N1;
    float ev[12];
    float mx = -INFINITY;
    #pragma unroll
    for (int t = 0; t < 12; t++){
        int i = lane + t*32;
        float a = ar[i];
        float e = (a > 0.f) ? er[i] : -9e15f;
        ev[t] = e;
        mx = fmaxf(mx, e);
    }
    #pragma unroll
    for (int o = 16; o; o >>= 1) mx = fmaxf(mx, __shfl_xor_sync(0xffffffffu, mx, o));
    float sum = 0.f;
    #pragma unroll
    for (int t = 0; t < 12; t++) sum += __expf(ev[t] - mx);
    #pragma unroll
    for (int o = 16; o; o >>= 1) sum += __shfl_xor_sync(0xffffffffu, sum, o);
    if (lane == 0){
        g_m [rg] = mx;
        g_iz[rg] = 1.f/sum;
    }
}

// ---------------- fuse: att on the fly, h'=relu(att@h), gate, next h/hA or pair-proj ----------------
__global__ __launch_bounds__(256) void k_fuse(const float* __restrict__ adj,
                                              const float* __restrict__ gW,
                                              const float* __restrict__ gb,
                                              const float* __restrict__ gatW,
                                              const float* __restrict__ gatWb,
                                              const float* __restrict__ pW1,
                                              const float* __restrict__ pb1,
                                              int l){
    int r0 = blockIdx.x*8;
    int b  = r0 / N1;
    int tid = threadIdx.x;
    int d = tid & 127, half = tid >> 7;
    int w = tid >> 5, lane = tid & 31;
    const float* hb = g_hX + (l & 1)*BB*N1*DD;
    __shared__ float s_att[8][N1];
    __shared__ float s_m [N1];
    __shared__ float s_iz[N1];
    __shared__ float s_g[8][DD];
    __shared__ float sx[8][DD];
    __shared__ float s_c[8];
    for (int idx = tid; idx < N1; idx += 256){
        s_m [idx] = g_m [b*N1 + idx];
        s_iz[idx] = g_iz[b*N1 + idx];
    }
    __syncthreads();
    #pragma unroll
    for (int ii = 0; ii < 8; ii++){
        const float* er = g_E + (size_t)(r0 + ii)*N1;
        const float* ar = adj + (size_t)(r0 + ii)*N1;
        for (int j = tid; j < N1; j += 256){
            float a = ar[j];
            float wv = 0.f;
            if (a > 0.f) wv = __expf(er[j] - s_m[j])*s_iz[j]*a;
            s_att[ii][j] = wv;
        }
    }
    float xd[4];
    #pragma unroll
    for (int q = 0; q < 4; q++) xd[q] = g_h1g[(r0 + half*4 + q)*DD + d];
    __syncthreads();
    float hp[4] = {0.f,0.f,0.f,0.f};
    const float* hcol = hb + b*N1*DD + d;
    #pragma unroll 4
    for (int j = 0; j < N1; j++){
        float hv = hcol[j*DD];
        #pragma unroll
        for (int q = 0; q < 4; q++) hp[q] = fmaf(s_att[half*4 + q][j], hv, hp[q]);
    }
    float gw1 = gW[l*2*DD + d], gw2 = gW[l*2*DD + DD + d], gbv = gb[l];
    #pragma unroll
    for (int q = 0; q < 4; q++){
        hp[q] = fmaxf(hp[q], 0.f);
        s_g[half*4 + q][d] = fmaf(xd[q], gw1, hp[q]*gw2);
    }
    __syncthreads();
    {   // warp w reduces row w
        float s = s_g[w][lane] + s_g[w][lane+32] + s_g[w][lane+64] + s_g[w][lane+96];
        #pragma unroll
        for (int o = 16; o; o >>= 1) s += __shfl_xor_sync(0xffffffffu, s, o);
        if (lane == 0) s_c[w] = sigmoidf_(s + gbv);
    }
    __syncthreads();
    #pragma unroll
    for (int q = 0; q < 4; q++){
        int row = half*4 + q;
        float coeff = s_c[row];
        float v = coeff*xd[q] + (1.f - coeff)*hp[q];
        g_h1g[(r0 + row)*DD + d] = v;
        sx[row][d] = v;
    }
    __syncthreads();
    if (l < LL-1){
        int nl = l + 1;
        const float* W  = gatW + nl*DD*DD;
        const float* WA = g_WA + nl*DD*DD;
        float wb = gatWb[nl*DD + d], bav = g_bA[nl*DD + d];
        float hh2[4], ha[4];
        #pragma unroll
        for (int q = 0; q < 4; q++){ hh2[q] = wb; ha[q] = bav; }
        #pragma unroll 2
        for (int k = 0; k < DD; k++){
            float wv  = W [k*DD + d];
            float wav = WA[k*DD + d];
            #pragma unroll
            for (int q = 0; q < 4; q++){
                hh2[q] += sx[half*4 + q][k]*wv;
                ha [q] += sx[half*4 + q][k]*wav;
            }
        }
        float* ho  = g_hX  + (nl & 1)*BB*N1*DD;
        float* hao = g_hAX + (nl & 1)*BB*N1*DD;
        #pragma unroll
        for (int q = 0; q < 4; q++){
            ho [(r0 + half*4 + q)*DD + d] = hh2[q];
            hao[(r0 + half*4 + q)*DD + d] = ha[q];
        }
    } else {
        // final layer: ligand pair projections for these 8 rows, all 5 MLPs
        for (int m = 0; m < 5; m++){
            const float* W = pW1 + m*2*DD*HH;
            float bias = pb1[m*HH + d];
            float acc[4];
            #pragma unroll
            for (int q = 0; q < 4; q++) acc[q] = bias;
            #pragma unroll 2
            for (int k = 0; k < DD; k++){
                float wv = W[k*HH + d];
                #pragma unroll
                for (int q = 0; q < 4; q++) acc[q] = fmaf(sx[half*4 + q][k], wv, acc[q]);
            }
            #pragma unroll
            for (int q = 0; q < 4; q++)
                g_p1[(m*BB*N1 + r0 + half*4 + q)*HH + d] = acc[q];
        }
    }
}

// ---------------- pair energies: 16i x 32j tile, float4 mainloop ----------------
__global__ __launch_bounds__(256) void k_pair(const float* __restrict__ dmv,
                                              const float* __restrict__ c1,
                                              const float* __restrict__ c2,
                                              const float* __restrict__ eps,
                                              const float* __restrict__ sig,
                                              const float* __restrict__ val1,
                                              const float* __restrict__ val2,
                                              const float* __restrict__ nmm1,
                                              const float* __restrict__ nmm2,
                                              const float* __restrict__ W2,
                                              const float* __restrict__ b2,
                                              const float* __restrict__ vdwc){
    int bix = blockIdx.x;          // j tile 0..11
    int biy = blockIdx.y;          // i tile 0..47
    int r0  = biy*16;
    int b   = r0 / N1;
    int i1  = r0 % N1;
    int j0  = bix*32;
    __shared__ float s_p1[16][132];
    __shared__ float s_p2[32][132];
    __shared__ float s_w2[5][128];
    __shared__ float s_b2v[5];
    __shared__ float s_red[16];
    int tid = threadIdx.x, lane = tid & 31, w = tid >> 5;
    int j  = lane;
    int ia = w*2;
    for (int idx = tid; idx < 5*DD; idx += 256) s_w2[idx/DD][idx%DD] = W2[idx];
    if (tid < 5) s_b2v[tid] = b2[tid];
    float acc[2][5];
    #pragma unroll
    for (int q = 0; q < 2; q++)
        #pragma unroll
        for (int m = 0; m < 5; m++) acc[q][m] = 0.f;
    for (int m = 0; m < 5; m++){
        __syncthreads();
        #pragma unroll
        for (int q = 0; q < 2; q++){
            int idx = tid + q*256;
            int row = idx >> 5, q4 = idx & 31;
            float4 v = *(const float4*)(g_p1 + (size_t)(m*BB*N1 + r0 + row)*HH + q4*4);
            *(float4*)&s_p1[row][q4*4] = v;
        }
        #pragma unroll
        for (int q = 0; q < 4; q++){
            int idx = tid + q*256;
            int row = idx >> 5, q4 = idx & 31;
            float4 v = *(const float4*)(g_p2 + (size_t)(m*BB*N2 + b*N2 + j0 + row)*HH + q4*4);
            *(float4*)&s_p2[row][q4*4] = v;
        }
        __syncthreads();
        float a0 = 0.f, a1 = 0.f;
        #pragma unroll
        for (int hv = 0; hv < 32; hv++){
            float4 w4  = *(const float4*)&s_w2[m][hv*4];
            float4 p2v = *(const float4*)&s_p2[j][hv*4];
            float4 pa  = *(const float4*)&s_p1[ia][hv*4];
            float4 pb  = *(const float4*)&s_p1[ia+1][hv*4];
            a0 = fmaf(fmaxf(pa.x + p2v.x, 0.f), w4.x, a0);
            a0 = fmaf(fmaxf(pa.y + p2v.y, 0.f), w4.y, a0);
            a0 = fmaf(fmaxf(pa.z + p2v.z, 0.f), w4.z, a0);
            a0 = fmaf(fmaxf(pa.w + p2v.w, 0.f), w4.w, a0);
            a1 = fmaf(fmaxf(pb.x + p2v.x, 0.f), w4.x, a1);
            a1 = fmaf(fmaxf(pb.y + p2v.y, 0.f), w4.y, a1);
            a1 = fmaf(fmaxf(pb.z + p2v.z, 0.f), w4.z, a1);
            a1 = fmaf(fmaxf(pb.w + p2v.w, 0.f), w4.w, a1);
        }
        acc[0][m] = a0; acc[1][m] = a1;
    }
    float vdwc2 = vdwc[0]*vdwc[0];
    float ec = 0.f, ev = 0.f;
    int jl = j0 + j;
    float c2v = c2[b*N2 + jl], v2v = val2[b*N2 + jl], n2v = nmm2[b*N2 + jl];
    #pragma unroll
    for (int q = 0; q < 2; q++){
        int il = i1 + ia + q;
        float v0 = acc[q][0] + s_b2v[0];
        float v1 = acc[q][1] + s_b2v[1];
        float v2 = acc[q][2] + s_b2v[2];
        float v3 = acc[q][3] + s_b2v[3];
        float v4 = acc[q][4] + s_b2v[4];
        int pix = (b*N1 + il)*N2 + jl;
        const float* dv = dmv + (size_t)pix*3;
        float dx = dv[0], dy = dv[1], dz = dv[2];
        float dm = sqrtf(dx*dx + dy*dy + dz*dz + 1e-10f);
        if (dm < 0.5f) dm = 1e10f;
        float l2dm = __log2f(dm);
        float cA  = sigmoidf_(v0);
        float cN  = 2.f*sigmoidf_(v1) + 1.f;
        float q12 = c1[b*N1 + il]*c2v;
        float e_c = cA*q12*exp2f(-cN*l2dm);
        e_c *= val1[b*N1 + il]*v2v;
        e_c = fminf(fmaxf(e_c, -100.f), 100.f);
        float vAv = (0.6f*sigmoidf_(v2) + 0.7f)*vdwc2*eps[pix];
        float vBv = tanhf(v3)*0.6f + 0.7f;
        float vNv = 2.f*sigmoidf_(v4) + 5.f;
        float dm0 = sig[pix]*vBv;
        if (dm0 < 1e-4f) dm0 = 1.f;
        float r  = exp2f(vNv*(__log2f(dm0) - l2dm));
        float e_v = vAv*(r*r - 2.f*r);
        e_v *= nmm1[b*N1 + il]*n2v;
        e_v = fminf(e_v, 100.f);
        ec += e_c; ev += e_v;
    }
    #pragma unroll
    for (int o = 16; o; o >>= 1){
        ec += __shfl_xor_sync(0xffffffffu, ec, o);
        ev += __shfl_xor_sync(0xffffffffu, ev, o);
    }
    if (lane == 0){ s_red[w] = ec; s_red[8 + w] = ev; }
    __syncthreads();
    if (tid == 0){
        float tec = 0.f, tev = 0.f;
        #pragma unroll
        for (int qq = 0; qq < 8; qq++){ tec += s_red[qq]; tev += s_red[8 + qq]; }
        g_pec[biy*12 + bix] = tec;
        g_pev[biy*12 + bix] = tev;
    }
}

// ---------------- finalize ----------------
__global__ __launch_bounds__(DD) void k_final(const float* __restrict__ valid1,
                                              const float* __restrict__ delta_uff,
                                              const float* __restrict__ duff,
                                              const float* __restrict__ iW1,
                                              const float* __restrict__ ib1,
                                              const float* __restrict__ iW2,
                                              const float* __restrict__ ib2,
                                              float* __restrict__ out){
    int b = blockIdx.x, d = threadIdx.x;
    __shared__ float s_hs[DD];
    __shared__ float s_red[DD];
    float hs = 0.f;
    for (int i = 0; i < N1; i++) hs += g_h1g[(b*N1 + i)*DD + d]*valid1[b*N1 + i];
    s_hs[d] = hs;
    __syncthreads();
    float hid = ib1[d];
    #pragma unroll 4
    for (int k = 0; k < DD; k++) hid += s_hs[k]*iW1[k*HH + d];
    hid = fmaxf(hid, 0.f);
    s_red[d] = hid*iW2[d];
    __syncthreads();
    for (int s = 64; s; s >>= 1){ if (d < s) s_red[d] += s_red[d + s]; __syncthreads(); }
    float inter = s_red[0] + ib2[0];
    __syncthreads();
    float tec = 0.f;
    for (int q = d; q < 288; q += DD) tec += g_pec[b*288 + q];
    s_red[d] = tec;
    __syncthreads();
    for (int s = 64; s; s >>= 1){ if (d < s) s_red[d] += s_red[d + s]; __syncthreads(); }
    float tecs = s_red[0];
    __syncthreads();
    float tev = 0.f;
    for (int q = d; q < 288; q += DD) tev += g_pev[b*288 + q];
    s_red[d] = tev;
    __syncthreads();
    for (int s = 64; s; s >>= 1){ if (d < s) s_red[d] += s_red[d + s]; __syncthreads(); }
    if (d == 0){
        out[b*4 + 0] = tecs;
        out[b*4 + 1] = s_red[0];
        out[b*4 + 2] = duff[0]*duff[0]*delta_uff[b];
        out[b*4 + 3] = inter;
    }
}

// ---------------- launch ----------------
// d_in follows setup_inputs() dict insertion order:
//   0:h1 1:h2 2:adj1 3:dmv 4:charge1 5:charge2 6:vdw_epsilon 7:vdw_sigma
//   8:delta_uff 9:valid1 10:valid2 11:no_metal1 12:no_metal2 13:node_W
//   14:gat_W 15:gat_Wb 16:gat_A 17:gat_gW 18:gat_gb 19:pair_W1 20:pair_b1
//   21:pair_W2 22:pair_b2 23:vdw_coeff 24:duff_coeff 25:int_W1 26:int_b1
//   27:int_W2 28:int_b2
extern "C" void kernel_launch(void* const* d_in, const int* in_sizes, int n_in,
                              void* d_out, int out_size){
    const float* h1        = (const float*)d_in[0];
    const float* h2        = (const float*)d_in[1];
    const float* adj1      = (const float*)d_in[2];
    const float* dmv       = (const float*)d_in[3];
    const float* charge1   = (const float*)d_in[4];
    const float* charge2   = (const float*)d_in[5];
    const float* eps       = (const float*)d_in[6];
    const float* sig       = (const float*)d_in[7];
    const float* delta_uff = (const float*)d_in[8];
    const float* valid1    = (const float*)d_in[9];
    const float* valid2    = (const float*)d_in[10];
    const float* nm1       = (const float*)d_in[11];
    const float* nm2       = (const float*)d_in[12];
    const float* nodeW     = (const float*)d_in[13];
    const float* gatW      = (const float*)d_in[14];
    const float* gatWb     = (const float*)d_in[15];
    const float* gatA      = (const float*)d_in[16];
    const float* gatgW     = (const float*)d_in[17];
    const float* gatgb     = (const float*)d_in[18];
    const float* pW1       = (const float*)d_in[19];
    const float* pb1       = (const float*)d_in[20];
    const float* pW2       = (const float*)d_in[21];
    const float* pb2       = (const float*)d_in[22];
    const float* vdwc      = (const float*)d_in[23];
    const float* duffc     = (const float*)d_in[24];
    const float* iW1       = (const float*)d_in[25];
    const float* ib1       = (const float*)d_in[26];
    const float* iW2       = (const float*)d_in[27];
    const float* ib2       = (const float*)d_in[28];
    float* out = (float*)d_out;

    static int attr_set = 0;
    if (!attr_set){
        cudaFuncSetAttribute(k_e, cudaFuncAttributeMaxDynamicSharedMemorySize, E_SMEM);
        attr_set = 1;
    }

    k_pre_node<<<LL*DD + (BB*(N1+N2))/4, 128>>>(gatW, gatWb, gatA, h1, h2, nodeW);
    k_stage2<<<96 + 240, 128>>>(gatW, gatWb, pW1);
    for (int l = 0; l < LL; l++){
        k_e    <<<dim3(N1/64, N1/32, BB), 256, E_SMEM>>>(l & 1);
        k_stats<<<BB*N1/8, 256>>>(adj1);
        k_fuse <<<BB*N1/8, 256>>>(adj1, gatgW, gatgb, gatW, gatWb, pW1, pb1, l);
    }
    k_pair<<<dim3(N2/32, BB*N1/16), 256>>>(dmv, charge1, charge2, eps, sig,
                                           valid1, valid2, nm1, nm2, pW2, pb2, vdwc);
    k_final<<<BB, DD>>>(valid1, delta_uff, duffc, iW1, ib1, iW2, ib2, out);
}

// round 8
// speedup vs baseline: 1.1669x; 1.1669x over previous
#include <cuda_runtime.h>
#include <math.h>

#define BB 2
#define N1 384
#define N2 384
#define DD 128
#define HH 128
#define LL 3
#define NF 54

// ---------------- scratch (device globals; no allocation) ----------------
static __device__ float g_h1g[BB*N1*DD];
static __device__ float g_h2g[BB*N2*DD];
static __device__ float g_hX [2*BB*N1*DD];   // ping-pong h
static __device__ float g_hAX[2*BB*N1*DD];   // ping-pong hA
static __device__ float g_P  [BB*N1*N1];
static __device__ float g_att[BB*N1*N1];
static __device__ float g_p1 [5*BB*N1*HH];
static __device__ float g_p2 [5*BB*N2*HH];
static __device__ float g_WA [LL*DD*DD];
static __device__ float g_bA [LL*DD];
static __device__ float g_pec[576];
static __device__ float g_pev[576];

__device__ __forceinline__ float sigmoidf_(float x){ return 1.f/(1.f+__expf(-x)); }

// ---------------- fused: WA=W@A, bA=Wb@A  +  node projection ----------------
__global__ __launch_bounds__(128) void k_pre_node(const float* __restrict__ W,
                                                  const float* __restrict__ Wb,
                                                  const float* __restrict__ A,
                                                  const float* __restrict__ h1,
                                                  const float* __restrict__ h2,
                                                  const float* __restrict__ nW){
    int bi = blockIdx.x, d = threadIdx.x;
    if (bi < LL*DD){
        int l = bi / DD, k = bi % DD;
        __shared__ float sw[DD];
        __shared__ float sb[DD];
        sw[d] = W[(l*DD + k)*DD + d];
        if (k == 0) sb[d] = Wb[l*DD + d];
        __syncthreads();
        const float* Al = A + l*DD*DD;
        float acc = 0.f;
        #pragma unroll 4
        for (int m = 0; m < DD; m++) acc += sw[m]*Al[m*DD + d];
        g_WA[(l*DD + k)*DD + d] = acc;
        if (k == 0){
            float bacc = 0.f;
            #pragma unroll 4
            for (int m = 0; m < DD; m++) bacc += sb[m]*Al[m*DD + d];
            g_bA[l*DD + d] = bacc;
        }
    } else {
        int r0 = (bi - LL*DD)*4;
        __shared__ float sx[4][NF];
        bool lig = (r0 < BB*N1);
        const float* src = lig ? (h1 + r0*NF) : (h2 + (r0 - BB*N1)*NF);
        for (int idx = d; idx < 4*NF; idx += 128) ((float*)sx)[idx] = src[idx];
        __syncthreads();
        float acc[4] = {0.f,0.f,0.f,0.f};
        #pragma unroll 2
        for (int k = 0; k < NF; k++){
            float wv = nW[k*DD + d];
            #pragma unroll
            for (int ii = 0; ii < 4; ii++) acc[ii] += sx[ii][k]*wv;
        }
        float* dst = lig ? (g_h1g + r0*DD) : (g_h2g + (r0 - BB*N1)*DD);
        #pragma unroll
        for (int ii = 0; ii < 4; ii++) dst[ii*DD + d] = acc[ii];
    }
}

// ---------------- stage2: gat_h layer0 (96 blocks) + protein pair-proj (240 blocks) ----------------
__global__ __launch_bounds__(128) void k_stage2(const float* __restrict__ gatW,
                                                const float* __restrict__ gatWb,
                                                const float* __restrict__ W1){
    int bi = blockIdx.x, d = threadIdx.x;
    __shared__ float sx[16][DD];
    if (bi < 96){
        int r0 = bi*8;
        #pragma unroll
        for (int ii = 0; ii < 8; ii++) sx[ii][d] = g_h1g[(r0 + ii)*DD + d];
        __syncthreads();
        float wb = gatWb[d], bav = g_bA[d];
        float h[8], ha[8];
        #pragma unroll
        for (int ii = 0; ii < 8; ii++){ h[ii] = wb; ha[ii] = bav; }
        #pragma unroll 2
        for (int k = 0; k < DD; k++){
            float wv  = gatW[k*DD + d];
            float wav = g_WA[k*DD + d];
            #pragma unroll
            for (int ii = 0; ii < 8; ii++){
                h [ii] += sx[ii][k]*wv;
                ha[ii] += sx[ii][k]*wav;
            }
        }
        #pragma unroll
        for (int ii = 0; ii < 8; ii++){
            g_hX [(r0 + ii)*DD + d] = h [ii];
            g_hAX[(r0 + ii)*DD + d] = ha[ii];
        }
    } else {
        int pi = bi - 96;
        int m  = pi / 48;
        int r0 = (pi % 48)*16;
        #pragma unroll
        for (int ii = 0; ii < 16; ii++) sx[ii][d] = g_h2g[(r0 + ii)*DD + d];
        __syncthreads();
        const float* W = W1 + m*2*DD*HH + DD*HH;   // protein half, no bias
        float acc[16];
        #pragma unroll
        for (int ii = 0; ii < 16; ii++) acc[ii] = 0.f;
        #pragma unroll 2
        for (int k = 0; k < DD; k++){
            float wv = W[k*HH + d];
            #pragma unroll
            for (int ii = 0; ii < 16; ii++) acc[ii] = fmaf(sx[ii][k], wv, acc[ii]);
        }
        #pragma unroll
        for (int ii = 0; ii < 16; ii++) g_p2[(m*BB*N2 + r0 + ii)*HH + d] = acc[ii];
    }
}

// ---------------- P = hA @ h^T : 32x64 tiles, 144 blocks ----------------
__global__ __launch_bounds__(256) void k_e(int cur){
    const float* hb  = g_hX  + cur*BB*N1*DD;
    const float* hab = g_hAX + cur*BB*N1*DD;
    int b = blockIdx.z, j0 = blockIdx.y*32, k0 = blockIdx.x*64;
    __shared__ float sA[64][36];
    __shared__ float sB[64][68];
    int tid = threadIdx.x;
    int tx = tid & 15, ty = tid >> 4;
    float acc[2][4];
    #pragma unroll
    for (int r = 0; r < 2; r++)
        #pragma unroll
        for (int c = 0; c < 4; c++) acc[r][c] = 0.f;
    const float* baseA = hab + (b*N1 + j0)*DD;
    const float* baseB = hb  + (b*N1 + k0)*DD;
    for (int ks = 0; ks < 2; ks++){
        __syncthreads();
        #pragma unroll
        for (int q = 0; q < 2; q++){
            int idx = tid + q*256;
            int row = idx & 31, kq = idx >> 5;
            float4 va = *(const float4*)(baseA + row*DD + ks*64 + kq*4);
            sA[kq*4+0][row] = va.x; sA[kq*4+1][row] = va.y;
            sA[kq*4+2][row] = va.z; sA[kq*4+3][row] = va.w;
        }
        #pragma unroll
        for (int q = 0; q < 4; q++){
            int idx = tid + q*256;
            int row = idx & 63, kq = idx >> 6;
            float4 vb = *(const float4*)(baseB + row*DD + ks*64 + kq*4);
            sB[kq*4+0][row] = vb.x; sB[kq*4+1][row] = vb.y;
            sB[kq*4+2][row] = vb.z; sB[kq*4+3][row] = vb.w;
        }
        __syncthreads();
        #pragma unroll 8
        for (int kk = 0; kk < 64; kk++){
            float2 av = *(const float2*)&sA[kk][ty*2];
            float4 bv = *(const float4*)&sB[kk][tx*4];
            acc[0][0] = fmaf(av.x, bv.x, acc[0][0]);
            acc[0][1] = fmaf(av.x, bv.y, acc[0][1]);
            acc[0][2] = fmaf(av.x, bv.z, acc[0][2]);
            acc[0][3] = fmaf(av.x, bv.w, acc[0][3]);
            acc[1][0] = fmaf(av.y, bv.x, acc[1][0]);
            acc[1][1] = fmaf(av.y, bv.y, acc[1][1]);
            acc[1][2] = fmaf(av.y, bv.z, acc[1][2]);
            acc[1][3] = fmaf(av.y, bv.w, acc[1][3]);
        }
    }
    #pragma unroll
    for (int r = 0; r < 2; r++){
        float4 o = make_float4(acc[r][0], acc[r][1], acc[r][2], acc[r][3]);
        *(float4*)&g_P[(b*N1 + j0 + ty*2 + r)*N1 + k0 + tx*4] = o;
    }
}

// ---------------- column softmax of e = P + P^T, masked by adj (16 cols/block) ----------------
#define SOFT_SMEM ((N1*17 + 16*385)*4)
__global__ __launch_bounds__(256) void k_soft(const float* __restrict__ adj){
    extern __shared__ float sm[];
    float* sCol = sm;             // [384][17]
    float* sRow = sm + N1*17;     // [16][385]
    int b  = blockIdx.y;
    int c0 = blockIdx.x*16;
    int tid = threadIdx.x;
    for (int idx = tid; idx < N1*16; idx += 256){
        int r = idx >> 4, c = idx & 15;
        float p = g_P[(b*N1 + r)*N1 + c0 + c];
        float a = adj[(b*N1 + r)*N1 + c0 + c];
        sCol[r*17 + c] = (a > 0.f) ? p : -9e15f;
    }
    for (int idx = tid; idx < 16*N1; idx += 256){
        int cc = idx / N1, r = idx % N1;
        sRow[cc*385 + r] = g_P[(b*N1 + c0 + cc)*N1 + r];
    }
    __syncthreads();
    int w = tid >> 5, lane = tid & 31;
    for (int cc = w; cc < 16; cc += 8){
        float ev[12];
        float mx = -INFINITY;
        #pragma unroll
        for (int t = 0; t < 12; t++){
            int r = lane + t*32;
            float e = sCol[r*17 + cc];
            if (e > -8e15f) e += sRow[cc*385 + r];
            ev[t] = e;
            mx = fmaxf(mx, e);
        }
        #pragma unroll
        for (int o = 16; o; o >>= 1) mx = fmaxf(mx, __shfl_xor_sync(0xffffffffu, mx, o));
        float sum = 0.f;
        #pragma unroll
        for (int t = 0; t < 12; t++){
            float x = __expf(ev[t] - mx);
            ev[t] = x; sum += x;
        }
        #pragma unroll
        for (int o = 16; o; o >>= 1) sum += __shfl_xor_sync(0xffffffffu, sum, o);
        float inv = 1.f/sum;
        #pragma unroll
        for (int t = 0; t < 12; t++) sCol[(lane + t*32)*17 + cc] = ev[t]*inv;
    }
    __syncthreads();
    for (int idx = tid; idx < N1*16; idx += 256){
        int r = idx >> 4, c = idx & 15;
        float a = adj[(b*N1 + r)*N1 + c0 + c];
        g_att[(b*N1 + r)*N1 + c0 + c] = sCol[r*17 + c]*a;
    }
}

// ---------------- fused: h'=relu(att@h), gated residual, then next-layer h/hA ----------------
__global__ __launch_bounds__(128) void k_fuse(const float* __restrict__ gW,
                                              const float* __restrict__ gb,
                                              const float* __restrict__ gatW,
                                              const float* __restrict__ gatWb,
                                              int l, int has_next){
    int r0 = blockIdx.x*8;
    int b  = r0 / N1;
    int d  = threadIdx.x;
    const float* hb = g_hX + (l & 1)*BB*N1*DD;
    __shared__ float s_att[8][N1];
    __shared__ float s_g[8][DD];
    __shared__ float s_c[8];
    __shared__ float sx[8][DD];
    for (int idx = d; idx < 8*N1; idx += DD){
        int ii = idx / N1, j = idx % N1;
        s_att[ii][j] = g_att[(r0 + ii)*N1 + j];
    }
    float xd[8];
    #pragma unroll
    for (int ii = 0; ii < 8; ii++) xd[ii] = g_h1g[(r0 + ii)*DD + d];
    __syncthreads();
    float hp[8];
    #pragma unroll
    for (int ii = 0; ii < 8; ii++) hp[ii] = 0.f;
    const float* hcol = hb + b*N1*DD + d;
    #pragma unroll 4
    for (int j = 0; j < N1; j++){
        float hv = hcol[j*DD];
        #pragma unroll
        for (int ii = 0; ii < 8; ii++) hp[ii] = fmaf(s_att[ii][j], hv, hp[ii]);
    }
    float gw1 = gW[l*2*DD + d], gw2 = gW[l*2*DD + DD + d], gbv = gb[l];
    #pragma unroll
    for (int ii = 0; ii < 8; ii++){
        hp[ii] = fmaxf(hp[ii], 0.f);
        s_g[ii][d] = fmaf(xd[ii], gw1, hp[ii]*gw2);
    }
    __syncthreads();
    int w = d >> 5, lane = d & 31;
    for (int ii = w; ii < 8; ii += 4){
        float s = s_g[ii][lane] + s_g[ii][lane+32] + s_g[ii][lane+64] + s_g[ii][lane+96];
        #pragma unroll
        for (int o = 16; o; o >>= 1) s += __shfl_xor_sync(0xffffffffu, s, o);
        if (lane == 0) s_c[ii] = sigmoidf_(s + gbv);
    }
    __syncthreads();
    #pragma unroll
    for (int ii = 0; ii < 8; ii++){
        float coeff = s_c[ii];
        float v = coeff*xd[ii] + (1.f - coeff)*hp[ii];
        g_h1g[(r0 + ii)*DD + d] = v;
        sx[ii][d] = v;
    }
    if (!has_next) return;
    __syncthreads();
    int nl = l + 1;
    const float* W  = gatW + nl*DD*DD;
    const float* WA = g_WA + nl*DD*DD;
    float wb  = gatWb[nl*DD + d];
    float bav = g_bA [nl*DD + d];
    float h[8], ha[8];
    #pragma unroll
    for (int ii = 0; ii < 8; ii++){ h[ii] = wb; ha[ii] = bav; }
    #pragma unroll 2
    for (int k = 0; k < DD; k++){
        float wv  = W [k*DD + d];
        float wav = WA[k*DD + d];
        #pragma unroll
        for (int ii = 0; ii < 8; ii++){
            h [ii] += sx[ii][k]*wv;
            ha[ii] += sx[ii][k]*wav;
        }
    }
    float* ho  = g_hX  + (nl & 1)*BB*N1*DD;
    float* hao = g_hAX + (nl & 1)*BB*N1*DD;
    #pragma unroll
    for (int ii = 0; ii < 8; ii++){
        ho [(r0 + ii)*DD + d] = h [ii];
        hao[(r0 + ii)*DD + d] = ha[ii];
    }
}

// ---------------- ligand pair projections (16 rows/block, 240 blocks) ----------------
__global__ __launch_bounds__(128) void k_proj1(const float* __restrict__ W1,
                                               const float* __restrict__ b1){
    int bi = blockIdx.x;
    int m  = bi / 48;
    int r0 = (bi % 48)*16;
    int hh = threadIdx.x;
    __shared__ float sx[16][DD];
    #pragma unroll
    for (int ii = 0; ii < 16; ii++) sx[ii][hh] = g_h1g[(r0 + ii)*DD + hh];
    __syncthreads();
    const float* W = W1 + m*2*DD*HH;
    float bias = b1[m*HH + hh];
    float acc[16];
    #pragma unroll
    for (int ii = 0; ii < 16; ii++) acc[ii] = bias;
    #pragma unroll 2
    for (int k = 0; k < DD; k++){
        float wv = W[k*HH + hh];
        #pragma unroll
        for (int ii = 0; ii < 16; ii++) acc[ii] = fmaf(sx[ii][k], wv, acc[ii]);
    }
    #pragma unroll
    for (int ii = 0; ii < 16; ii++) g_p1[(m*BB*N1 + r0 + ii)*HH + hh] = acc[ii];
}

// ---------------- pair energies: 16i x 32j tile, float4 mainloop ----------------
__global__ __launch_bounds__(256) void k_pair(const float* __restrict__ dmv,
                                              const float* __restrict__ c1,
                                              const float* __restrict__ c2,
                                              const float* __restrict__ eps,
                                              const float* __restrict__ sig,
                                              const float* __restrict__ val1,
                                              const float* __restrict__ val2,
                                              const float* __restrict__ nmm1,
                                              const float* __restrict__ nmm2,
                                              const float* __restrict__ W2,
                                              const float* __restrict__ b2,
                                              const float* __restrict__ vdwc){
    int bix = blockIdx.x;          // j tile 0..11
    int biy = blockIdx.y;          // i tile 0..47
    int r0  = biy*16;
    int b   = r0 / N1;
    int i1  = r0 % N1;
    int j0  = bix*32;
    __shared__ float s_p1[16][132];
    __shared__ float s_p2[32][132];
    __shared__ float s_w2[5][128];
    __shared__ float s_b2v[5];
    __shared__ float s_red[16];
    int tid = threadIdx.x, lane = tid & 31, w = tid >> 5;
    int j  = lane;
    int ia = w*2;
    for (int idx = tid; idx < 5*DD; idx += 256) s_w2[idx/DD][idx%DD] = W2[idx];
    if (tid < 5) s_b2v[tid] = b2[tid];
    float acc[2][5];
    #pragma unroll
    for (int q = 0; q < 2; q++)
        #pragma unroll
        for (int m = 0; m < 5; m++) acc[q][m] = 0.f;
    for (int m = 0; m < 5; m++){
        __syncthreads();
        #pragma unroll
        for (int q = 0; q < 2; q++){
            int idx = tid + q*256;
            int row = idx >> 5, q4 = idx & 31;
            float4 v = *(const float4*)(g_p1 + (size_t)(m*BB*N1 + r0 + row)*HH + q4*4);
            *(float4*)&s_p1[row][q4*4] = v;
        }
        #pragma unroll
        for (int q = 0; q < 4; q++){
            int idx = tid + q*256;
            int row = idx >> 5, q4 = idx & 31;
            float4 v = *(const float4*)(g_p2 + (size_t)(m*BB*N2 + b*N2 + j0 + row)*HH + q4*4);
            *(float4*)&s_p2[row][q4*4] = v;
        }
        __syncthreads();
        float a0 = 0.f, a1 = 0.f;
        #pragma unroll
        for (int hv = 0; hv < 32; hv++){
            float4 w4  = *(const float4*)&s_w2[m][hv*4];
            float4 p2v = *(const float4*)&s_p2[j][hv*4];
            float4 pa  = *(const float4*)&s_p1[ia][hv*4];
            float4 pb  = *(const float4*)&s_p1[ia+1][hv*4];
            a0 = fmaf(fmaxf(pa.x + p2v.x, 0.f), w4.x, a0);
            a0 = fmaf(fmaxf(pa.y + p2v.y, 0.f), w4.y, a0);
            a0 = fmaf(fmaxf(pa.z + p2v.z, 0.f), w4.z, a0);
            a0 = fmaf(fmaxf(pa.w + p2v.w, 0.f), w4.w, a0);
            a1 = fmaf(fmaxf(pb.x + p2v.x, 0.f), w4.x, a1);
            a1 = fmaf(fmaxf(pb.y + p2v.y, 0.f), w4.y, a1);
            a1 = fmaf(fmaxf(pb.z + p2v.z, 0.f), w4.z, a1);
            a1 = fmaf(fmaxf(pb.w + p2v.w, 0.f), w4.w, a1);
        }
        acc[0][m] = a0; acc[1][m] = a1;
    }
    float vdwc2 = vdwc[0]*vdwc[0];
    float ec = 0.f, ev = 0.f;
    int jl = j0 + j;
    float c2v = c2[b*N2 + jl], v2v = val2[b*N2 + jl], n2v = nmm2[b*N2 + jl];
    #pragma unroll
    for (int q = 0; q < 2; q++){
        int il = i1 + ia + q;
        float v0 = acc[q][0] + s_b2v[0];
        float v1 = acc[q][1] + s_b2v[1];
        float v2 = acc[q][2] + s_b2v[2];
        float v3 = acc[q][3] + s_b2v[3];
        float v4 = acc[q][4] + s_b2v[4];
        int pix = (b*N1 + il)*N2 + jl;
        const float* dv = dmv + (size_t)pix*3;
        float dx = dv[0], dy = dv[1], dz = dv[2];
        float dm = sqrtf(dx*dx + dy*dy + dz*dz + 1e-10f);
        if (dm < 0.5f) dm = 1e10f;
        float l2dm = __log2f(dm);
        float cA  = sigmoidf_(v0);
        float cN  = 2.f*sigmoidf_(v1) + 1.f;
        float q12 = c1[b*N1 + il]*c2v;
        float e_c = cA*q12*exp2f(-cN*l2dm);
        e_c *= val1[b*N1 + il]*v2v;
        e_c = fminf(fmaxf(e_c, -100.f), 100.f);
        float vAv = (0.6f*sigmoidf_(v2) + 0.7f)*vdwc2*eps[pix];
        float vBv = tanhf(v3)*0.6f + 0.7f;
        float vNv = 2.f*sigmoidf_(v4) + 5.f;
        float dm0 = sig[pix]*vBv;
        if (dm0 < 1e-4f) dm0 = 1.f;
        float r  = exp2f(vNv*(__log2f(dm0) - l2dm));
        float e_v = vAv*(r*r - 2.f*r);
        e_v *= nmm1[b*N1 + il]*n2v;
        e_v = fminf(e_v, 100.f);
        ec += e_c; ev += e_v;
    }
    #pragma unroll
    for (int o = 16; o; o >>= 1){
        ec += __shfl_xor_sync(0xffffffffu, ec, o);
        ev += __shfl_xor_sync(0xffffffffu, ev, o);
    }
    if (lane == 0){ s_red[w] = ec; s_red[8 + w] = ev; }
    __syncthreads();
    if (tid == 0){
        float tec = 0.f, tev = 0.f;
        #pragma unroll
        for (int qq = 0; qq < 8; qq++){ tec += s_red[qq]; tev += s_red[8 + qq]; }
        g_pec[biy*12 + bix] = tec;
        g_pev[biy*12 + bix] = tev;
    }
}

// ---------------- finalize ----------------
__global__ __launch_bounds__(DD) void k_final(const float* __restrict__ valid1,
                                              const float* __restrict__ delta_uff,
                                              const float* __restrict__ duff,
                                              const float* __restrict__ iW1,
                                              const float* __restrict__ ib1,
                                              const float* __restrict__ iW2,
                                              const float* __restrict__ ib2,
                                              float* __restrict__ out){
    int b = blockIdx.x, d = threadIdx.x;
    __shared__ float s_hs[DD];
    __shared__ float s_red[DD];
    float hs = 0.f;
    for (int i = 0; i < N1; i++) hs += g_h1g[(b*N1 + i)*DD + d]*valid1[b*N1 + i];
    s_hs[d] = hs;
    __syncthreads();
    float hid = ib1[d];
    #pragma unroll 4
    for (int k = 0; k < DD; k++) hid += s_hs[k]*iW1[k*HH + d];
    hid = fmaxf(hid, 0.f);
    s_red[d] = hid*iW2[d];
    __syncthreads();
    for (int s = 64; s; s >>= 1){ if (d < s) s_red[d] += s_red[d + s]; __syncthreads(); }
    float inter = s_red[0] + ib2[0];
    __syncthreads();
    float tec = 0.f;
    for (int q = d; q < 288; q += DD) tec += g_pec[b*288 + q];
    s_red[d] = tec;
    __syncthreads();
    for (int s = 64; s; s >>= 1){ if (d < s) s_red[d] += s_red[d + s]; __syncthreads(); }
    float tecs = s_red[0];
    __syncthreads();
    float tev = 0.f;
    for (int q = d; q < 288; q += DD) tev += g_pev[b*288 + q];
    s_red[d] = tev;
    __syncthreads();
    for (int s = 64; s; s >>= 1){ if (d < s) s_red[d] += s_red[d + s]; __syncthreads(); }
    if (d == 0){
        out[b*4 + 0] = tecs;
        out[b*4 + 1] = s_red[0];
        out[b*4 + 2] = duff[0]*duff[0]*delta_uff[b];
        out[b*4 + 3] = inter;
    }
}

// ---------------- launch ----------------
// d_in follows setup_inputs() dict insertion order:
//   0:h1 1:h2 2:adj1 3:dmv 4:charge1 5:charge2 6:vdw_epsilon 7:vdw_sigma
//   8:delta_uff 9:valid1 10:valid2 11:no_metal1 12:no_metal2 13:node_W
//   14:gat_W 15:gat_Wb 16:gat_A 17:gat_gW 18:gat_gb 19:pair_W1 20:pair_b1
//   21:pair_W2 22:pair_b2 23:vdw_coeff 24:duff_coeff 25:int_W1 26:int_b1
//   27:int_W2 28:int_b2
extern "C" void kernel_launch(void* const* d_in, const int* in_sizes, int n_in,
                              void* d_out, int out_size){
    const float* h1        = (const float*)d_in[0];
    const float* h2        = (const float*)d_in[1];
    const float* adj1      = (const float*)d_in[2];
    const float* dmv       = (const float*)d_in[3];
    const float* charge1   = (const float*)d_in[4];
    const float* charge2   = (const float*)d_in[5];
    const float* eps       = (const float*)d_in[6];
    const float* sig       = (const float*)d_in[7];
    const float* delta_uff = (const float*)d_in[8];
    const float* valid1    = (const float*)d_in[9];
    const float* valid2    = (const float*)d_in[10];
    const float* nm1       = (const float*)d_in[11];
    const float* nm2       = (const float*)d_in[12];
    const float* nodeW     = (const float*)d_in[13];
    const float* gatW      = (const float*)d_in[14];
    const float* gatWb     = (const float*)d_in[15];
    const float* gatA      = (const float*)d_in[16];
    const float* gatgW     = (const float*)d_in[17];
    const float* gatgb     = (const float*)d_in[18];
    const float* pW1       = (const float*)d_in[19];
    const float* pb1       = (const float*)d_in[20];
    const float* pW2       = (const float*)d_in[21];
    const float* pb2       = (const float*)d_in[22];
    const float* vdwc      = (const float*)d_in[23];
    const float* duffc     = (const float*)d_in[24];
    const float* iW1       = (const float*)d_in[25];
    const float* ib1       = (const float*)d_in[26];
    const float* iW2       = (const float*)d_in[27];
    const float* ib2       = (const float*)d_in[28];
    float* out = (float*)d_out;

    static int attr_set = 0;
    if (!attr_set){
        cudaFuncSetAttribute(k_soft, cudaFuncAttributeMaxDynamicSharedMemorySize, SOFT_SMEM);
        attr_set = 1;
    }

    k_pre_node<<<LL*DD + (BB*(N1+N2))/4, 128>>>(gatW, gatWb, gatA, h1, h2, nodeW);
    k_stage2<<<96 + 240, 128>>>(gatW, gatWb, pW1);
    for (int l = 0; l < LL; l++){
        k_e   <<<dim3(N1/64, N1/32, BB), 256>>>(l & 1);
        k_soft<<<dim3(N1/16, BB), 256, SOFT_SMEM>>>(adj1);
        k_fuse<<<BB*N1/8, 128>>>(gatgW, gatgb, gatW, gatWb, l, (l < LL-1) ? 1 : 0);
    }
    k_proj1<<<240, 128>>>(pW1, pb1);
    k_pair<<<dim3(N2/32, BB*N1/16), 256>>>(dmv, charge1, charge2, eps, sig,
                                           valid1, valid2, nm1, nm2, pW2, pb2, vdwc);
    k_final<<<BB, DD>>>(valid1, delta_uff, duffc, iW1, ib1, iW2, ib2, out);
}